// round 1
// baseline (speedup 1.0000x reference)
#include <cuda_runtime.h>
#include <math.h>

// Transformer-XL relative attention, fused flash-style fp32 baseline.
// B=2 H=16 Q=1024 K=2048 D=64.
// BD_shifted[i,j] = (q[i]+vT) . r[j-i+1023]  for j <= i+1024, else 0.

#define QS 68    // padded stride for 64-wide tiles
#define RS 132   // padded stride for 128-wide band tiles

#define OFF_QU 0
#define OFF_QV (64*QS)
#define OFF_KT (2*64*QS)
#define OFF_VS (3*64*QS)
#define OFF_RB (4*64*QS)
#define OFF_BD (4*64*QS + 64*RS)
#define OFF_PS (4*64*QS + 2*64*RS)
#define SMEM_FLOATS (5*64*QS + 2*64*RS)

__global__ __launch_bounds__(256, 1)
void relattn_kernel(const float* __restrict__ q, const float* __restrict__ kk,
                    const float* __restrict__ v, const float* __restrict__ r,
                    const float* __restrict__ uT, const float* __restrict__ wT,
                    float* __restrict__ out)
{
    extern __shared__ float sm[];
    float* quS = sm + OFF_QU;   // [64][QS] q + uT
    float* qvS = sm + OFF_QV;   // [64][QS] q + vT
    float* kT  = sm + OFF_KT;   // [64 d][QS jl] transposed K tile
    float* vS  = sm + OFF_VS;   // [64 jl][QS d] V tile
    float* rbT = sm + OFF_RB;   // [64 d][RS pl] transposed r band (128 rows)
    float* bdS = sm + OFF_BD;   // [64 il][RS pl] BD band
    float* pS  = sm + OFF_PS;   // [64 il][QS jl] probabilities

    const int tid = threadIdx.x;
    const int tx = tid & 15;
    const int ty = tid >> 4;
    const int bh = blockIdx.y;          // b*16 + h
    const int h  = bh & 15;
    const int i0 = blockIdx.x << 6;     // q-tile base

    const float* qg = q  + ((size_t)bh * 1024 + i0) * 64;
    const float* kg = kk + (size_t)bh * 2048 * 64;
    const float* vg = v  + (size_t)bh * 2048 * 64;
    const float* rg = r  + (size_t)h  * 2048 * 64;
    const float* ug = uT + h * 64;
    const float* wg = wT + h * 64;

    // ---- load qu = q+uT, qv = q+vT (once per CTA) ----
    for (int e = tid; e < 1024; e += 256) {
        int row = e >> 4, dc = (e & 15) << 2;
        float4 qq = *(const float4*)(qg + row * 64 + dc);
        float4 uu = *(const float4*)(ug + dc);
        float4 vv = *(const float4*)(wg + dc);
        *(float4*)(quS + row * QS + dc) =
            make_float4(qq.x + uu.x, qq.y + uu.y, qq.z + uu.z, qq.w + uu.w);
        *(float4*)(qvS + row * QS + dc) =
            make_float4(qq.x + vv.x, qq.y + vv.y, qq.z + vv.z, qq.w + vv.w);
    }

    float acc[4][4] = {};
    float mrow[4], lrow[4];
    #pragma unroll
    for (int i = 0; i < 4; i++) { mrow[i] = -INFINITY; lrow[i] = 0.f; }

    const int il0 = ty << 2;   // 4 q-rows per thread
    const int jl0 = tx << 2;   // 4 k-cols / d-cols per thread
    const int pl0 = tx << 3;   // 8 band-cols per thread

    for (int j0 = 0; j0 < 2048; j0 += 64) {
        __syncthreads();   // prior PV done / qu ready before overwriting tiles

        // ---- K tile, transposed into kT[d][jl] ----
        for (int e = tid; e < 1024; e += 256) {
            int jl = e & 63, dc = (e >> 6) << 2;
            float4 kv = *(const float4*)(kg + (size_t)(j0 + jl) * 64 + dc);
            kT[(dc + 0) * QS + jl] = kv.x;
            kT[(dc + 1) * QS + jl] = kv.y;
            kT[(dc + 2) * QS + jl] = kv.z;
            kT[(dc + 3) * QS + jl] = kv.w;
        }
        // ---- V tile row-major ----
        for (int e = tid; e < 1024; e += 256) {
            int jl = e >> 4, dc = (e & 15) << 2;
            *(float4*)(vS + jl * QS + dc) =
                *(const float4*)(vg + (size_t)(j0 + jl) * 64 + dc);
        }
        // ---- r band transposed: p = p0 + pl, pl in [0,128) ----
        int p0 = j0 - i0 + 960;  // (j-i+1023) = p0 + (jl-il+63)
        for (int e = tid; e < 2048; e += 256) {
            int pl = e & 127, dc = (e >> 7) << 2;
            int p = p0 + pl;
            float4 rv = make_float4(0.f, 0.f, 0.f, 0.f);
            if (p >= 0 && p < 2048)
                rv = *(const float4*)(rg + (size_t)p * 64 + dc);
            rbT[(dc + 0) * RS + pl] = rv.x;
            rbT[(dc + 1) * RS + pl] = rv.y;
            rbT[(dc + 2) * RS + pl] = rv.z;
            rbT[(dc + 3) * RS + pl] = rv.w;
        }
        __syncthreads();

        // ---- BD band GEMM: bdS[il][pl] = qv[il] . rbT[:, pl] ----
        {
            float Ba[4][8] = {};
            #pragma unroll 2
            for (int d = 0; d < 64; d++) {
                float4 r0 = *(const float4*)(rbT + d * RS + pl0);
                float4 r1 = *(const float4*)(rbT + d * RS + pl0 + 4);
                float rb[8] = {r0.x, r0.y, r0.z, r0.w, r1.x, r1.y, r1.z, r1.w};
                #pragma unroll
                for (int rr = 0; rr < 4; rr++) {
                    float a = qvS[(il0 + rr) * QS + d];
                    #pragma unroll
                    for (int cc = 0; cc < 8; cc++) Ba[rr][cc] += a * rb[cc];
                }
            }
            #pragma unroll
            for (int rr = 0; rr < 4; rr++) {
                *(float4*)(bdS + (il0 + rr) * RS + pl0) =
                    make_float4(Ba[rr][0], Ba[rr][1], Ba[rr][2], Ba[rr][3]);
                *(float4*)(bdS + (il0 + rr) * RS + pl0 + 4) =
                    make_float4(Ba[rr][4], Ba[rr][5], Ba[rr][6], Ba[rr][7]);
            }
        }

        // ---- AC GEMM (doesn't touch bdS) ----
        float S[4][4] = {};
        #pragma unroll
        for (int d = 0; d < 64; d += 4) {
            float4 a[4], bk[4];
            #pragma unroll
            for (int rr = 0; rr < 4; rr++)
                a[rr] = *(const float4*)(quS + (il0 + rr) * QS + d);
            #pragma unroll
            for (int dd = 0; dd < 4; dd++)
                bk[dd] = *(const float4*)(kT + (d + dd) * QS + jl0);
            #pragma unroll
            for (int rr = 0; rr < 4; rr++) {
                S[rr][0] += a[rr].x*bk[0].x + a[rr].y*bk[1].x + a[rr].z*bk[2].x + a[rr].w*bk[3].x;
                S[rr][1] += a[rr].x*bk[0].y + a[rr].y*bk[1].y + a[rr].z*bk[2].y + a[rr].w*bk[3].y;
                S[rr][2] += a[rr].x*bk[0].z + a[rr].y*bk[1].z + a[rr].z*bk[2].z + a[rr].w*bk[3].z;
                S[rr][3] += a[rr].x*bk[0].w + a[rr].y*bk[1].w + a[rr].z*bk[2].w + a[rr].w*bk[3].w;
            }
        }
        __syncthreads();  // bdS fully written before gather

        // ---- gather shifted BD, scale ----
        #pragma unroll
        for (int rr = 0; rr < 4; rr++) {
            #pragma unroll
            for (int cc = 0; cc < 4; cc++) {
                int pl = jl0 + cc - (il0 + rr) + 63;   // in [0,126]
                S[rr][cc] = (S[rr][cc] + bdS[(il0 + rr) * RS + pl]) * 0.125f;
            }
        }

        // ---- online softmax over 16-lane row groups ----
        #pragma unroll
        for (int rr = 0; rr < 4; rr++) {
            float mx = fmaxf(fmaxf(S[rr][0], S[rr][1]), fmaxf(S[rr][2], S[rr][3]));
            #pragma unroll
            for (int w = 1; w < 16; w <<= 1)
                mx = fmaxf(mx, __shfl_xor_sync(0xffffffffu, mx, w));
            float mn = fmaxf(mrow[rr], mx);
            float al = __expf(mrow[rr] - mn);   // first tile: exp(-inf)=0
            mrow[rr] = mn;
            float s = 0.f;
            #pragma unroll
            for (int cc = 0; cc < 4; cc++) {
                S[rr][cc] = __expf(S[rr][cc] - mn);
                s += S[rr][cc];
            }
            #pragma unroll
            for (int w = 1; w < 16; w <<= 1)
                s += __shfl_xor_sync(0xffffffffu, s, w);
            lrow[rr] = lrow[rr] * al + s;
            #pragma unroll
            for (int cc = 0; cc < 4; cc++) acc[rr][cc] *= al;
            *(float4*)(pS + (il0 + rr) * QS + jl0) =
                make_float4(S[rr][0], S[rr][1], S[rr][2], S[rr][3]);
        }
        __syncthreads();

        // ---- PV: acc[il][d] += P[il][jl] * V[jl][d] ----
        #pragma unroll 4
        for (int jl = 0; jl < 64; jl++) {
            float4 vv = *(const float4*)(vS + jl * QS + jl0);
            #pragma unroll
            for (int rr = 0; rr < 4; rr++) {
                float p = pS[(il0 + rr) * QS + jl];
                acc[rr][0] += p * vv.x;
                acc[rr][1] += p * vv.y;
                acc[rr][2] += p * vv.z;
                acc[rr][3] += p * vv.w;
            }
        }
    }

    // ---- epilogue ----
    float* og = out + ((size_t)bh * 1024 + i0) * 64;
    #pragma unroll
    for (int rr = 0; rr < 4; rr++) {
        float inv = 1.f / lrow[rr];
        *(float4*)(og + (il0 + rr) * 64 + jl0) =
            make_float4(acc[rr][0] * inv, acc[rr][1] * inv,
                        acc[rr][2] * inv, acc[rr][3] * inv);
    }
}

extern "C" void kernel_launch(void* const* d_in, const int* in_sizes, int n_in,
                              void* d_out, int out_size)
{
    const float* q  = (const float*)d_in[0];
    const float* k  = (const float*)d_in[1];
    const float* v  = (const float*)d_in[2];
    const float* r  = (const float*)d_in[3];
    const float* uT = (const float*)d_in[4];
    const float* vT = (const float*)d_in[5];
    // d_in[6] = mask: all-ones AND unused by the reference body — ignored.

    cudaFuncSetAttribute(relattn_kernel,
                         cudaFuncAttributeMaxDynamicSharedMemorySize,
                         SMEM_FLOATS * sizeof(float));

    dim3 grid(16, 32);   // 16 q-tiles x (B*H)=32
    relattn_kernel<<<grid, 256, SMEM_FLOATS * sizeof(float)>>>(
        q, k, v, r, uT, vT, (float*)d_out);
}